// round 12
// baseline (speedup 1.0000x reference)
#include <cuda_runtime.h>
#include <math.h>

#define BSZ   8
#define TT    1024
#define DD    512
#define HH    8
#define DKK   64
#define FFD   2048
#define NROWS (BSZ*TT)      // 8192
#define NBH   (BSZ*HH)      // 64

// ------------------------- static scratch (device globals) -----------------
__device__ float g_x   [NROWS*DD];
__device__ float g_y   [NROWS*DD];
__device__ float g_xpad[BSZ*(TT+4)*DD];
__device__ float g_scr [NROWS*DD];
__device__ float g_kh  [NBH*TT*DKK];
__device__ float g_vh  [NBH*TT*DKK];
__device__ float g_att [(size_t)NBH*TT*TT];   // 256 MB
__device__ float g_cc  [NROWS*DD];
__device__ float g_ffh [NROWS*FFD];

// ------------------------- pad: left-pad 4 zero timesteps ------------------
__global__ void pad_kernel(const float* __restrict__ x, float* __restrict__ xp)
{
    int idx = blockIdx.x * 256 + threadIdx.x;
    const int total = BSZ*(TT+4)*DD;
    if (idx >= total) return;
    int d = idx % DD;
    int p = (idx / DD) % (TT+4);
    int b = idx / (DD*(TT+4));
    xp[idx] = (p < 4) ? 0.f : x[((long)b*TT + (p-4))*DD + d];
}

// ------------------------- NN GEMM (tile 128x64x16, 256 thr, 8x4) ----------
// epi: 0 row-major (ldc) | 1 head layout [B,H,T,DK] | 2 concat from batched AV
__global__ void __launch_bounds__(256) gemm_nn(
    const float* __restrict__ A, const float* __restrict__ B,
    const float* __restrict__ bias, float* __restrict__ C,
    int K, int lda, int ldb, int ldc,
    long aBatch, long bBatch,
    int epi, int relu, int causalK)
{
    __shared__ float As[16][132];
    __shared__ float Bs[16][64];
    const int rowBase = blockIdx.y * 128;
    const int colBase = blockIdx.x * 64;
    if (causalK && K > rowBase + 128) K = rowBase + 128;

    const float* Ab = A + (long)blockIdx.z * aBatch;
    const float* Bb = B + (long)blockIdx.z * bBatch;
    const int tid = threadIdx.x;
    const int tx = tid & 15, ty = tid >> 4;

    float acc[8][4];
#pragma unroll
    for (int m = 0; m < 8; m++)
#pragma unroll
        for (int n = 0; n < 4; n++) acc[m][n] = 0.f;

    for (int k0 = 0; k0 < K; k0 += 16) {
#pragma unroll
        for (int i = 0; i < 8; i++) {
            int idx = tid + i * 256;
            int r = idx >> 4, c = idx & 15;
            As[c][r] = Ab[(long)(rowBase + r) * lda + (k0 + c)];
        }
#pragma unroll
        for (int i = 0; i < 4; i++) {
            int idx = tid + i * 256;
            int r = idx >> 6, c = idx & 63;
            Bs[r][c] = Bb[(long)(k0 + r) * ldb + (colBase + c)];
        }
        __syncthreads();
#pragma unroll
        for (int k = 0; k < 16; k++) {
            float4 a0 = *(const float4*)&As[k][ty*8];
            float4 a1 = *(const float4*)&As[k][ty*8+4];
            float4 b4 = *(const float4*)&Bs[k][tx*4];
            float am[8] = {a0.x,a0.y,a0.z,a0.w,a1.x,a1.y,a1.z,a1.w};
            float bn[4] = {b4.x,b4.y,b4.z,b4.w};
#pragma unroll
            for (int m = 0; m < 8; m++)
#pragma unroll
                for (int n = 0; n < 4; n++)
                    acc[m][n] = fmaf(am[m], bn[n], acc[m][n]);
        }
        __syncthreads();
    }

    float4 bv = make_float4(0.f,0.f,0.f,0.f);
    if (bias) bv = *(const float4*)&bias[colBase + tx*4];
    const int col = colBase + tx*4;
#pragma unroll
    for (int m = 0; m < 8; m++) {
        int row = rowBase + ty*8 + m;
        float4 o = make_float4(acc[m][0]+bv.x, acc[m][1]+bv.y,
                               acc[m][2]+bv.z, acc[m][3]+bv.w);
        if (relu) {
            o.x=fmaxf(o.x,0.f); o.y=fmaxf(o.y,0.f);
            o.z=fmaxf(o.z,0.f); o.w=fmaxf(o.w,0.f);
        }
        long idx;
        if (epi == 0) {
            idx = (long)row*ldc + col;
        } else if (epi == 1) {               // [B,T,D] -> [B,H,T,DK]
            int b = row >> 10, t = row & 1023, h = col >> 6, dk = col & 63;
            idx = (((long)((b<<3) | h) * 1024 + t) << 6) + dk;
        } else {                             // batched AV -> concat [B,T,D]
            int b = blockIdx.z >> 3, h = blockIdx.z & 7;
            idx = (((long)b*1024 + row) * 512) + (h<<6) + col;
        }
        *(float4*)&C[idx] = o;
    }
}

// ------------------------- NT GEMM: C = alpha*A@B^T + beta*C ---------------
// A rows via row-groups (padded conv input); B element-strided (conv taps).
__global__ void __launch_bounds__(256) gemm_nt(
    const float* __restrict__ A, const float* __restrict__ B,
    float* __restrict__ C,
    int K, int lda, int ldc,
    long aBatch, long bBatch, long cBatch,
    int rgSize, long rgStride, int rowOff,
    long ldbRow, int bStride,
    float alpha, float beta, int causalSkip)
{
    const int rowBase = blockIdx.y * 128;
    const int colBase = blockIdx.x * 64;
    if (causalSkip && colBase > rowBase + 127) return;

    __shared__ float As[16][132];
    __shared__ float Bs[16][68];
    const float* Ab = A + (long)blockIdx.z * aBatch;
    const float* Bb = B + (long)blockIdx.z * bBatch;
    const int tid = threadIdx.x;
    const int tx = tid & 15, ty = tid >> 4;

    float acc[8][4];
#pragma unroll
    for (int m = 0; m < 8; m++)
#pragma unroll
        for (int n = 0; n < 4; n++) acc[m][n] = 0.f;

    for (int k0 = 0; k0 < K; k0 += 16) {
#pragma unroll
        for (int i = 0; i < 8; i++) {
            int idx = tid + i * 256;
            int r = idx >> 4, c = idx & 15;
            int gr = rowBase + r;
            long ar = (long)(gr / rgSize) * rgStride
                    + (long)((gr % rgSize) + rowOff) * lda;
            As[c][r] = Ab[ar + k0 + c];
        }
#pragma unroll
        for (int i = 0; i < 4; i++) {
            int idx = tid + i * 256;
            int kk = idx & 15, n = idx >> 4;
            Bs[kk][n] = Bb[(long)(colBase + n) * ldbRow + (long)(k0 + kk) * bStride];
        }
        __syncthreads();
#pragma unroll
        for (int k = 0; k < 16; k++) {
            float4 a0 = *(const float4*)&As[k][ty*8];
            float4 a1 = *(const float4*)&As[k][ty*8+4];
            float4 b4 = *(const float4*)&Bs[k][tx*4];
            float am[8] = {a0.x,a0.y,a0.z,a0.w,a1.x,a1.y,a1.z,a1.w};
            float bn[4] = {b4.x,b4.y,b4.z,b4.w};
#pragma unroll
            for (int m = 0; m < 8; m++)
#pragma unroll
                for (int n = 0; n < 4; n++)
                    acc[m][n] = fmaf(am[m], bn[n], acc[m][n]);
        }
        __syncthreads();
    }

    const int col = colBase + tx*4;
#pragma unroll
    for (int m = 0; m < 8; m++) {
        int row = rowBase + ty*8 + m;
        long idx = (long)blockIdx.z * cBatch + (long)row * ldc + col;
        float4 o = make_float4(alpha*acc[m][0], alpha*acc[m][1],
                               alpha*acc[m][2], alpha*acc[m][3]);
        if (beta != 0.f) {
            float4 p = *(const float4*)&C[idx];
            o.x += beta*p.x; o.y += beta*p.y; o.z += beta*p.z; o.w += beta*p.w;
        }
        *(float4*)&C[idx] = o;
    }
}

// ------------------------- decay-attention row kernel ----------------------
// One block = one (bh, q) row. In place: raw scores -> final probabilities.
__global__ void __launch_bounds__(256) attn_kernel(
    float* __restrict__ S, const float* __restrict__ gam, int mtype)
{
    const int q  = blockIdx.x;
    const int bh = blockIdx.y;
    float* row = S + ((long)bh * TT + q) * TT;
    const int tid   = threadIdx.x;
    const int kbase = tid * 4;
    const int kmax  = mtype ? q : (q - 1);

    __shared__ float red[256];

    if (kmax < 0) {               // all-masked row == zero_pad row (mtype 0, q 0)
        *(float4*)&row[kbase] = make_float4(0.f,0.f,0.f,0.f);
        return;
    }

    float4 v4 = *(const float4*)&row[kbase];
    float v[4] = {v4.x, v4.y, v4.z, v4.w};

    // softmax #1: max
    float mx = -3.0e38f;
#pragma unroll
    for (int j = 0; j < 4; j++) if (kbase + j <= kmax) mx = fmaxf(mx, v[j]);
    red[tid] = mx; __syncthreads();
    for (int s = 128; s > 0; s >>= 1) {
        if (tid < s) red[tid] = fmaxf(red[tid], red[tid+s]);
        __syncthreads();
    }
    mx = red[0]; __syncthreads();

    // softmax #1: sum
    float e[4]; float ls = 0.f;
#pragma unroll
    for (int j = 0; j < 4; j++) {
        e[j] = (kbase + j <= kmax) ? __expf(v[j] - mx) : 0.f;
        ls += e[j];
    }
    red[tid] = ls; __syncthreads();
    for (int s = 128; s > 0; s >>= 1) {
        if (tid < s) red[tid] += red[tid+s];
        __syncthreads();
    }
    float rz = 1.f / red[0]; __syncthreads();

    // inclusive cumsum of s_ (local + Hillis-Steele block scan)
    float c[4]; float run = 0.f;
#pragma unroll
    for (int j = 0; j < 4; j++) { run += e[j] * rz; c[j] = run; }
    red[tid] = run; __syncthreads();
    for (int off = 1; off < 256; off <<= 1) {
        float t = (tid >= off) ? red[tid - off] : 0.f;
        __syncthreads();
        red[tid] += t;
        __syncthreads();
    }
    float excl = red[tid] - run;
    __syncthreads();

    // distance effect + softmax #2   (disttot == 1 for valid rows)
    float gamma = -log1pf(expf(gam[bh & 7]));
    float s2[4]; float mx2 = -3.0e38f;
#pragma unroll
    for (int j = 0; j < 4; j++) {
        int k = kbase + j;
        if (k <= kmax) {
            float rem  = fmaxf(1.f - (excl + c[j]), 0.f);
            float dist = sqrtf(rem * (float)(q - k));
            float eff  = __expf(dist * gamma);
            eff = fminf(fmaxf(eff, 1e-5f), 1e5f);
            s2[j] = v[j] * eff;
            mx2 = fmaxf(mx2, s2[j]);
        } else {
            s2[j] = -3.0e38f;
        }
    }
    red[tid] = mx2; __syncthreads();
    for (int s = 128; s > 0; s >>= 1) {
        if (tid < s) red[tid] = fmaxf(red[tid], red[tid+s]);
        __syncthreads();
    }
    mx2 = red[0]; __syncthreads();

    float e2[4]; float ls2 = 0.f;
#pragma unroll
    for (int j = 0; j < 4; j++) {
        e2[j] = (kbase + j <= kmax) ? __expf(s2[j] - mx2) : 0.f;
        ls2 += e2[j];
    }
    red[tid] = ls2; __syncthreads();
    for (int s = 128; s > 0; s >>= 1) {
        if (tid < s) red[tid] += red[tid+s];
        __syncthreads();
    }
    float rz2 = 1.f / red[0];

    *(float4*)&row[kbase] = make_float4(e2[0]*rz2, e2[1]*rz2, e2[2]*rz2, e2[3]*rz2);
}

// ------------------------- LayerNorm helpers -------------------------------
__device__ __forceinline__ float blockSum128(float v, float* sm)
{
#pragma unroll
    for (int o = 16; o; o >>= 1) v += __shfl_xor_sync(0xffffffffu, v, o);
    if ((threadIdx.x & 31) == 0) sm[threadIdx.x >> 5] = v;
    __syncthreads();
    v = sm[0] + sm[1] + sm[2] + sm[3];
    __syncthreads();
    return v;
}

__global__ void __launch_bounds__(128) ln_res_kernel(
    const float* __restrict__ a, const float* __restrict__ b,
    const float* __restrict__ g, const float* __restrict__ bt,
    float eps, float* __restrict__ out)
{
    const long row = blockIdx.x;
    const int tid = threadIdx.x;
    __shared__ float sm[4];
    const float4 av = *(const float4*)&a[row*DD + tid*4];
    const float4 bv = *(const float4*)&b[row*DD + tid*4];
    float v0 = av.x+bv.x, v1 = av.y+bv.y, v2 = av.z+bv.z, v3 = av.w+bv.w;
    float mean = blockSum128(v0+v1+v2+v3, sm) * (1.f/512.f);
    float d0=v0-mean, d1=v1-mean, d2=v2-mean, d3=v3-mean;
    float var = blockSum128(d0*d0+d1*d1+d2*d2+d3*d3, sm) * (1.f/512.f);
    float rstd = rsqrtf(var + eps);
    const float4 gv  = *(const float4*)&g[tid*4];
    const float4 btv = *(const float4*)&bt[tid*4];
    float4 o = make_float4(gv.x*d0*rstd + btv.x, gv.y*d1*rstd + btv.y,
                           gv.z*d2*rstd + btv.z, gv.w*d3*rstd + btv.w);
    *(float4*)&out[row*DD + tid*4] = o;
}

// smooth combine + LN(eps=1e-12): tr=trend+cb; val=tr+sb^2*(x-tr)+x; LN(val)
__global__ void __launch_bounds__(128) smooth_ln_kernel(
    const float* __restrict__ x, const float* __restrict__ trend,
    const float* __restrict__ cb, const float* __restrict__ sb,
    const float* __restrict__ g, const float* __restrict__ bt,
    float* __restrict__ out)
{
    const long row = blockIdx.x;
    const int tid = threadIdx.x;
    __shared__ float sm[4];
    const float4 xv = *(const float4*)&x[row*DD + tid*4];
    const float4 tv = *(const float4*)&trend[row*DD + tid*4];
    const float4 cv = *(const float4*)&cb[tid*4];
    const float4 sv = *(const float4*)&sb[tid*4];
    float v[4];
    { float tr = tv.x + cv.x, s2 = sv.x*sv.x; v[0] = tr + s2*(xv.x - tr) + xv.x; }
    { float tr = tv.y + cv.y, s2 = sv.y*sv.y; v[1] = tr + s2*(xv.y - tr) + xv.y; }
    { float tr = tv.z + cv.z, s2 = sv.z*sv.z; v[2] = tr + s2*(xv.z - tr) + xv.z; }
    { float tr = tv.w + cv.w, s2 = sv.w*sv.w; v[3] = tr + s2*(xv.w - tr) + xv.w; }
    float mean = blockSum128(v[0]+v[1]+v[2]+v[3], sm) * (1.f/512.f);
    float d0=v[0]-mean, d1=v[1]-mean, d2=v[2]-mean, d3=v[3]-mean;
    float var = blockSum128(d0*d0+d1*d1+d2*d2+d3*d3, sm) * (1.f/512.f);
    float rstd = rsqrtf(var + 1e-12f);
    const float4 gv  = *(const float4*)&g[tid*4];
    const float4 btv = *(const float4*)&bt[tid*4];
    float4 o = make_float4(gv.x*d0*rstd + btv.x, gv.y*d1*rstd + btv.y,
                           gv.z*d2*rstd + btv.z, gv.w*d3*rstd + btv.w);
    *(float4*)&out[row*DD + tid*4] = o;
}

// ------------------------- host enqueue ------------------------------------
struct Params {
    const float *conv_w, *conv_b, *sqrt_beta, *sm_g, *sm_b;
    const float *k_w, *k_b, *v_w, *v_b, *out_w, *out_b, *gammas;
    const float *ln1_g, *ln1_b, *ff1_w, *ff1_b, *ff2_w, *ff2_b, *ln2_g, *ln2_b;
};

static void enqueue_smooth(const float* inp, float* out, float* xpad,
                           float* trend, const Params& P)
{
    const int total = BSZ*(TT+4)*DD;
    pad_kernel<<<(total + 255)/256, 256>>>(inp, xpad);
    for (int tap = 0; tap < 5; tap++) {
        gemm_nt<<<dim3(DD/64, NROWS/128, 1), 256>>>(
            xpad, P.conv_w + tap, trend,
            512, 512, 512,
            0L, 0L, 0L,
            1024, (long)(TT+4)*DD, tap,
            (long)DD*5, 5,
            1.f, tap ? 1.f : 0.f, 0);
    }
    smooth_ln_kernel<<<NROWS, 128>>>(inp, trend, P.conv_b, P.sqrt_beta,
                                     P.sm_g, P.sm_b, out);
}

static void enqueue_layer(int i, float* x, const float* vin, int mtype, int ffn,
                          float* ln2_out,
                          float* kh, float* vh, float* att, float* cc,
                          float* scr, float* ffh, const Params& P)
{
    // K projection (q == k) -> head layout
    gemm_nn<<<dim3(8, 64, 1), 256>>>(x, P.k_w + (long)i*DD*DD, P.k_b + i*DD, kh,
        512, 512, 512, 0, 0L, 0L, 1, 0, 0);
    // V projection -> head layout
    gemm_nn<<<dim3(8, 64, 1), 256>>>(vin, P.v_w + (long)i*DD*DD, P.v_b + i*DD, vh,
        512, 512, 512, 0, 0L, 0L, 1, 0, 0);
    // scores = K K^T / 8, batched over (b,h), skip above-diagonal blocks
    gemm_nt<<<dim3(16, 8, 64), 256>>>(kh, kh, att,
        64, 64, 1024,
        (long)TT*DKK, (long)TT*DKK, (long)TT*TT,
        1024, 0L, 0,
        64L, 1,
        0.125f, 0.f, 1);
    // decay attention (in place)
    attn_kernel<<<dim3(1024, 64), 256>>>(att, P.gammas + i*HH, mtype);
    // O = P @ V -> concat layout, causal-K clamp
    gemm_nn<<<dim3(1, 8, 64), 256>>>(att, vh, (const float*)0, cc,
        1024, 1024, 64, 0, (long)TT*TT, (long)TT*DKK, 2, 0, 1);
    // out projection
    gemm_nn<<<dim3(8, 64, 1), 256>>>(cc, P.out_w + (long)i*DD*DD,
        P.out_b + i*DD, scr, 512, 512, 512, 512, 0L, 0L, 0, 0, 0);
    // x = LN(x + q2)
    ln_res_kernel<<<NROWS, 128>>>(x, scr, P.ln1_g + i*DD, P.ln1_b + i*DD,
                                  1e-5f, x);
    if (ffn) {
        gemm_nn<<<dim3(FFD/64, 64, 1), 256>>>(x, P.ff1_w + (long)i*DD*FFD,
            P.ff1_b + i*FFD, ffh, 512, 512, FFD, FFD, 0L, 0L, 0, 1, 0);
        gemm_nn<<<dim3(8, 64, 1), 256>>>(ffh, P.ff2_w + (long)i*FFD*DD,
            P.ff2_b + i*DD, scr, FFD, FFD, 512, 512, 0L, 0L, 0, 0, 0);
        ln_res_kernel<<<NROWS, 128>>>(x, scr, P.ln2_g + i*DD, P.ln2_b + i*DD,
                                      1e-5f, ln2_out ? ln2_out : x);
    }
}

extern "C" void kernel_launch(void* const* d_in, const int* in_sizes, int n_in,
                              void* d_out, int out_size)
{
    Params P;
    P.conv_w    = (const float*)d_in[3];
    P.conv_b    = (const float*)d_in[4];
    P.sqrt_beta = (const float*)d_in[5];
    P.sm_g      = (const float*)d_in[6];
    P.sm_b      = (const float*)d_in[7];
    P.k_w   = (const float*)d_in[8];
    P.k_b   = (const float*)d_in[9];
    P.v_w   = (const float*)d_in[10];
    P.v_b   = (const float*)d_in[11];
    P.out_w = (const float*)d_in[12];
    P.out_b = (const float*)d_in[13];
    P.gammas = (const float*)d_in[14];
    P.ln1_g = (const float*)d_in[15];
    P.ln1_b = (const float*)d_in[16];
    P.ff1_w = (const float*)d_in[17];
    P.ff1_b = (const float*)d_in[18];
    P.ff2_w = (const float*)d_in[19];
    P.ff2_b = (const float*)d_in[20];
    P.ln2_g = (const float*)d_in[21];
    P.ln2_b = (const float*)d_in[22];
    const float* q_emb  = (const float*)d_in[0];
    const float* qa_emb = (const float*)d_in[1];
    float* out = (float*)d_out;

    float *x, *y, *xpad, *scr, *kh, *vh, *att, *cc, *ffh;
    cudaGetSymbolAddress((void**)&x,    g_x);
    cudaGetSymbolAddress((void**)&y,    g_y);
    cudaGetSymbolAddress((void**)&xpad, g_xpad);
    cudaGetSymbolAddress((void**)&scr,  g_scr);
    cudaGetSymbolAddress((void**)&kh,   g_kh);
    cudaGetSymbolAddress((void**)&vh,   g_vh);
    cudaGetSymbolAddress((void**)&att,  g_att);
    cudaGetSymbolAddress((void**)&cc,   g_cc);
    cudaGetSymbolAddress((void**)&ffh,  g_ffh);

    // smooth both streams
    enqueue_smooth(q_emb,  x, xpad, scr, P);
    enqueue_smooth(qa_emb, y, xpad, scr, P);

    // blocks_1: two self-attn layers on y (mask=1, FFN)
    enqueue_layer(0, y, y, 1, 1, 0, kh, vh, att, cc, scr, ffh, P);
    enqueue_layer(1, y, y, 1, 1, 0, kh, vh, att, cc, scr, ffh, P);
    // blocks_2
    enqueue_layer(2, x, x, 1, 0, 0,   kh, vh, att, cc, scr, ffh, P);
    enqueue_layer(3, x, y, 0, 1, 0,   kh, vh, att, cc, scr, ffh, P);
    enqueue_layer(4, x, x, 1, 0, 0,   kh, vh, att, cc, scr, ffh, P);
    enqueue_layer(5, x, y, 0, 1, out, kh, vh, att, cc, scr, ffh, P);
}